// round 16
// baseline (speedup 1.0000x reference)
#include <cuda_runtime.h>
#include <cstdint>

// Problem constants
#define BB   64
#define TT   2048
#define II   200
#define HH   100
#define G4   400   // 4*H

// Scratch: xg[t][b][j] (t-major so scan CTA b streams coalesced rows), ~210MB.
__device__ float g_xg[(size_t)TT * BB * G4];
// Transposed W_ih: Wt[k][j] = W_ih[j][k]  (200 x 400) for coalesced loads.
__device__ float g_Wt[II * G4];

// ---- packed fp32x2 helpers ---------------------------------------------
union f2u { float2 f; unsigned long long u; };
union f4u { float4 f; ulonglong2 u; };

__device__ __forceinline__ unsigned long long ffma2(unsigned long long a,
                                                    unsigned long long b,
                                                    unsigned long long c) {
    unsigned long long d;
    asm("fma.rn.f32x2 %0, %1, %2, %3;" : "=l"(d) : "l"(a), "l"(b), "l"(c));
    return d;
}
__device__ __forceinline__ unsigned long long fadd2(unsigned long long a,
                                                    unsigned long long b) {
    unsigned long long d;
    asm("add.rn.f32x2 %0, %1, %2;" : "=l"(d) : "l"(a), "l"(b));
    return d;
}
__device__ __forceinline__ float tanh_(float x) {
    return __fdividef(2.0f, 1.0f + __expf(-2.0f * x)) - 1.0f;
}

// ---- kernel 0: transpose W_ih (R1 verbatim) -----------------------------
__global__ void transpose_wih(const float* __restrict__ Wih) {
    int o = blockIdx.x * 256 + threadIdx.x;   // o = k*400 + j (coalesced write)
    if (o < II * G4) {
        int k = o / G4;
        int j = o - k * G4;
        g_Wt[o] = Wih[j * II + k];
    }
}

// ---- kernel 1: input projection (R1 verbatim — measured ~245us) ---------
// xg[t][b][j] = sum_i x[b][t][i] * W_ih[j][i] + (b_ih[j]+b_hh[j])
// Tile: 32 timesteps (rows) x 400 cols per CTA. grid = (T/32, B).
// x staged ONCE per CTA (one barrier total); entire K=200 loop is
// barrier-free, weights streamed coalesced from L2 via g_Wt.
#define R_TILE 32
#define XS_STRIDE 44   // padded row stride (floats); 44*4=176 is 16B aligned

__global__ __launch_bounds__(400, 2)
void proj_kernel(const float* __restrict__ x,
                 const float* __restrict__ bih,
                 const float* __restrict__ bhh) {
    __shared__ float xs[II * XS_STRIDE];   // xs[k][r], 35.2 KB

    const int b  = blockIdx.y;
    const int t0 = blockIdx.x * R_TILE;
    const int j  = threadIdx.x;            // 0..399

    // Stage x[b][t0:t0+32][0:200] (contiguous 6400 floats) transposed to xs[k][r]
    const float* xsrc = x + ((size_t)b * TT + t0) * II;
    for (int idx = j; idx < R_TILE * II; idx += 400) {
        int r = idx / II;
        int k = idx - r * II;
        xs[k * XS_STRIDE + r] = xsrc[idx];
    }
    __syncthreads();

    unsigned long long acc[R_TILE / 2];
    #pragma unroll
    for (int q = 0; q < R_TILE / 2; ++q) acc[q] = 0ULL;

    #pragma unroll 4
    for (int k = 0; k < II; ++k) {
        float w = g_Wt[k * G4 + j];        // coalesced, L2-resident
        f2u wv; wv.f.x = w; wv.f.y = w;
        const float4* hp = (const float4*)&xs[k * XS_STRIDE];
        #pragma unroll
        for (int q = 0; q < R_TILE / 4; ++q) {
            f4u v; v.f = hp[q];            // rows 4q..4q+3 (warp-broadcast LDS.128)
            acc[2 * q]     = ffma2(wv.u, v.u.x, acc[2 * q]);
            acc[2 * q + 1] = ffma2(wv.u, v.u.y, acc[2 * q + 1]);
        }
    }

    const float bias = bih[j] + bhh[j];
    #pragma unroll
    for (int r = 0; r < R_TILE; ++r) {
        f2u a; a.u = acc[r >> 1];
        float val = ((r & 1) ? a.f.y : a.f.x) + bias;
        g_xg[((size_t)(t0 + r) * BB + b) * G4 + j] = val;
    }
}

// ---- kernel 2: sequential LSTM scan (R6 — best measured, unchanged) -----
// One CTA per batch row, 400 threads. Threads 4j..4j+3 own the i,f,g,o
// gates of hidden unit j (same quad) -> combine via quad shfl.
// h double-buffered (1 barrier/step). xg prefetched a FULL GROUP (4 steps)
// ahead via a register ring.
#define SG 4   // steps per prefetch group (TT % SG == 0)

__global__ __launch_bounds__(400, 1)
void scan_kernel(const float* __restrict__ Whh, float* __restrict__ out) {
    const int b    = blockIdx.x;
    const int tid  = threadIdx.x;
    const int j    = tid >> 2;     // hidden unit 0..99
    const int g    = tid & 3;      // gate: 0=i 1=f 2=g 3=o
    const unsigned qmask = 0xFu << ((tid & 31) & ~3);   // this thread's quad

    __shared__ __align__(16) float h_sh[2][HH];

    // W_hh row (g*100 + j), 100 floats -> 25 float4 in registers
    f4u wreg[HH / 4];
    const float4* wr = (const float4*)(Whh + (size_t)(g * HH + j) * HH);
    #pragma unroll
    for (int q = 0; q < HH / 4; ++q) wreg[q].f = wr[q];

    float c = 0.0f, hval = 0.0f;
    if (tid < HH) h_sh[0][tid] = 0.0f;
    __syncthreads();

    const float* xg = g_xg + (size_t)b * G4 + (g * HH + j);
    const size_t tstride = (size_t)BB * G4;

    float cur[SG], nxt[SG];
    #pragma unroll
    for (int i = 0; i < SG; ++i) cur[i] = __ldcs(&xg[(size_t)i * tstride]);

    int p = 0;
    for (int tg = 0; tg < TT; tg += SG) {
        // issue next group's loads NOW (consumed >= SG steps from now)
        #pragma unroll
        for (int i = 0; i < SG; ++i) {
            int tt = tg + SG + i;
            tt = (tt < TT) ? tt : (TT - 1);
            nxt[i] = __ldcs(&xg[(size_t)tt * tstride]);
        }

        #pragma unroll
        for (int i = 0; i < SG; ++i) {
            // 4 independent accumulation chains (depth ~13 each)
            unsigned long long a0 = 0ULL, a1 = 0ULL, a2 = 0ULL, a3 = 0ULL;
            const float4* hb = (const float4*)h_sh[p];
            #pragma unroll
            for (int q = 0; q < HH / 4; ++q) {
                f4u h4; h4.f = hb[q];            // broadcast LDS.128
                if (q & 1) {
                    a2 = ffma2(wreg[q].u.x, h4.u.x, a2);
                    a3 = ffma2(wreg[q].u.y, h4.u.y, a3);
                } else {
                    a0 = ffma2(wreg[q].u.x, h4.u.x, a0);
                    a1 = ffma2(wreg[q].u.y, h4.u.y, a1);
                }
            }
            f2u s0, s1;
            s0.u = fadd2(a0, a2);
            s1.u = fadd2(a1, a3);
            float gate = (s0.f.x + s0.f.y) + (s1.f.x + s1.f.y) + cur[i];

            // branch-free activation: g==2 -> tanh = 2*sig(2x)-1, else sigmoid
            bool is_t = (g == 2);
            float xx = is_t ? 2.0f * gate : gate;
            float s  = __fdividef(1.0f, 1.0f + __expf(-xx));
            float a  = is_t ? fmaf(2.0f, s, -1.0f) : s;

            // quad combine (lanes of this quad, all converged)
            float fg = __shfl_down_sync(qmask, a, 1, 4);
            float gg = __shfl_down_sync(qmask, a, 2, 4);
            float og = __shfl_down_sync(qmask, a, 3, 4);
            if (g == 0) {
                c    = fg * c + a * gg;
                hval = og * tanh_(c);
                h_sh[p ^ 1][j] = hval;           // write OTHER buffer
            }
            __syncthreads();
            p ^= 1;
        }

        #pragma unroll
        for (int i = 0; i < SG; ++i) cur[i] = nxt[i];
    }

    if (g == 0) out[b * HH + j] = hval;
}

// ---- launch ------------------------------------------------------------
extern "C" void kernel_launch(void* const* d_in, const int* in_sizes, int n_in,
                              void* d_out, int out_size) {
    const float* x   = (const float*)d_in[0];   // [64,2048,200]
    const float* Wih = (const float*)d_in[1];   // [400,200]
    const float* Whh = (const float*)d_in[2];   // [400,100]
    const float* bih = (const float*)d_in[3];   // [400]
    const float* bhh = (const float*)d_in[4];   // [400]
    float* out = (float*)d_out;                 // [64,100]

    transpose_wih<<<(II * G4 + 255) / 256, 256>>>(Wih);
    proj_kernel<<<dim3(TT / R_TILE, BB), 400>>>(x, bih, bhh);
    scan_kernel<<<BB, 400>>>(Whh, out);
}

// round 17
// speedup vs baseline: 1.2528x; 1.2528x over previous
#include <cuda_runtime.h>
#include <cstdint>

// Problem constants
#define BB   64
#define TT   2048
#define II   200
#define HH   100
#define G4   400   // 4*H

// Scratch: xg[t][b][j] (t-major so scan CTA b streams coalesced rows), ~210MB.
__device__ float g_xg[(size_t)TT * BB * G4];

// ---- packed fp32x2 helpers ---------------------------------------------
union f2u { float2 f; unsigned long long u; };
union f4u { float4 f; ulonglong2 u; };

__device__ __forceinline__ unsigned long long ffma2(unsigned long long a,
                                                    unsigned long long b,
                                                    unsigned long long c) {
    unsigned long long d;
    asm("fma.rn.f32x2 %0, %1, %2, %3;" : "=l"(d) : "l"(a), "l"(b), "l"(c));
    return d;
}
__device__ __forceinline__ unsigned long long fadd2(unsigned long long a,
                                                    unsigned long long b) {
    unsigned long long d;
    asm("add.rn.f32x2 %0, %1, %2;" : "=l"(d) : "l"(a), "l"(b));
    return d;
}
__device__ __forceinline__ float sig_(float x) {
    return __fdividef(1.0f, 1.0f + __expf(-x));
}
__device__ __forceinline__ float tanh_(float x) {
    return __fdividef(2.0f, 1.0f + __expf(-2.0f * x)) - 1.0f;
}

// ---- kernel 1: input projection (R6 version — part of the 2083us best) --
// C[131072, 400] = x[131072, 200] @ W_ih^T  (+bias) -> g_xg[t][b][col]
// CTA tile: 64 rows x 100 cols (grid 2048 x 4). 200 threads, thread tile 8x4.
#define KC 20
#define AS_STRIDE 68   // 68*4=272B, 16B aligned

__global__ __launch_bounds__(200, 4)
void proj_kernel(const float* __restrict__ x,
                 const float* __restrict__ Wih,
                 const float* __restrict__ bih,
                 const float* __restrict__ bhh) {
    __shared__ float As[KC * AS_STRIDE];   // As[k][r], 5.44 KB
    __shared__ float Bs[KC * HH];          // Bs[k][jc], 8 KB

    const int tid  = threadIdx.x;
    const int tx   = tid % 25;             // col group: cols tx*4 .. tx*4+3
    const int ty   = tid / 25;             // row group: rows ty*8 .. ty*8+7
    const int row0 = blockIdx.x * 64;
    const int c0   = blockIdx.y * HH;      // global column base (0/100/200/300)

    unsigned long long acc[8][2];
    #pragma unroll
    for (int r = 0; r < 8; ++r) { acc[r][0] = 0ULL; acc[r][1] = 0ULL; }

    for (int cch = 0; cch < II / KC; ++cch) {
        const int k0 = cch * KC;
        __syncthreads();   // previous chunk fully consumed

        // Stage A: 64 rows x 20 k, transposed to As[k][r]. 320 float4 loads.
        for (int idx = tid; idx < 64 * (KC / 4); idx += 200) {
            int r = idx / (KC / 4);
            int q = idx - r * (KC / 4);
            float4 v = *(const float4*)&x[(size_t)(row0 + r) * II + k0 + 4 * q];
            As[(4 * q + 0) * AS_STRIDE + r] = v.x;
            As[(4 * q + 1) * AS_STRIDE + r] = v.y;
            As[(4 * q + 2) * AS_STRIDE + r] = v.z;
            As[(4 * q + 3) * AS_STRIDE + r] = v.w;
        }
        // Stage B (transposing): thread t<100 owns W_ih row j=c0+t (L2-resident)
        if (tid < HH) {
            const float* wrow = &Wih[(size_t)(c0 + tid) * II + k0];
            #pragma unroll
            for (int q = 0; q < KC / 4; ++q) {
                float4 v = *(const float4*)&wrow[4 * q];
                Bs[(4 * q + 0) * HH + tid] = v.x;
                Bs[(4 * q + 1) * HH + tid] = v.y;
                Bs[(4 * q + 2) * HH + tid] = v.z;
                Bs[(4 * q + 3) * HH + tid] = v.w;
            }
        }
        __syncthreads();

        #pragma unroll 4
        for (int k = 0; k < KC; ++k) {
            f4u a0, a1, w0;
            a0.f = *(const float4*)&As[k * AS_STRIDE + ty * 8];
            a1.f = *(const float4*)&As[k * AS_STRIDE + ty * 8 + 4];
            w0.f = *(const float4*)&Bs[k * HH + tx * 4];
            float ar[8] = {a0.f.x, a0.f.y, a0.f.z, a0.f.w,
                           a1.f.x, a1.f.y, a1.f.z, a1.f.w};
            #pragma unroll
            for (int r = 0; r < 8; ++r) {
                f2u av; av.f.x = ar[r]; av.f.y = ar[r];
                acc[r][0] = ffma2(av.u, w0.u.x, acc[r][0]);
                acc[r][1] = ffma2(av.u, w0.u.y, acc[r][1]);
            }
        }
    }

    // Epilogue: add bias, scatter rows to g_xg[t][b][col]
    const int col = c0 + tx * 4;
    f4u bi, bh;
    bi.f = *(const float4*)&bih[col];
    bh.f = *(const float4*)&bhh[col];
    float4 bias = make_float4(bi.f.x + bh.f.x, bi.f.y + bh.f.y,
                              bi.f.z + bh.f.z, bi.f.w + bh.f.w);

    #pragma unroll
    for (int r = 0; r < 8; ++r) {
        int m = row0 + ty * 8 + r;
        int b = m >> 11;           // m / 2048
        int t = m & 2047;
        f2u p0, p1;
        p0.u = acc[r][0]; p1.u = acc[r][1];
        float4 o = make_float4(p0.f.x + bias.x, p0.f.y + bias.y,
                               p1.f.x + bias.z, p1.f.y + bias.w);
        *(float4*)&g_xg[((size_t)t * BB + b) * G4 + col] = o;
    }
}

// ---- kernel 2: sequential LSTM scan — 200 threads, TWO GATES PER THREAD -
// One CTA per batch row, 200 threads (6.25 warps). Thread pair (2j, 2j+1)
// owns hidden unit j: gp=0 computes full dots for gates i,f; gp=1 for g,o.
// Both gates' 100-float weight rows live in registers (~200 regs; cap at
// 200 thr is 255 — legal, unlike the 128/163-pinned variants that spilled).
// Each h float4 (25 LDS/step) feeds FOUR FFMA2 -> per-SMSP issue load drops
// ~35% vs the 400-thread quad layout. Tail: i,f are already local to the
// leader; only g,o cross via 2 width-2 shfls. One barrier/step, h double-
// buffered, xg prefetched 2 steps ahead.
__global__ __launch_bounds__(200, 1)
void scan_kernel(const float* __restrict__ Whh, float* __restrict__ out) {
    const int b   = blockIdx.x;
    const int tid = threadIdx.x;        // 0..199
    const int j   = tid >> 1;           // hidden unit 0..99
    const int gp  = tid & 1;            // 0: gates {i,f}, 1: gates {g,o}
    const int g0  = gp * 2;             // first gate row block
    const unsigned pmask = 0x3u << ((tid & 31) & ~1);   // this pair's lanes

    __shared__ __align__(16) float h_sh[2][HH];

    // Two W_hh rows in registers: gate g0 (wA) and g0+1 (wB), 25 float4 each.
    f4u wA[HH / 4], wB[HH / 4];
    {
        const float4* rA = (const float4*)(Whh + (size_t)(g0 * HH + j) * HH);
        const float4* rB = (const float4*)(Whh + (size_t)((g0 + 1) * HH + j) * HH);
        #pragma unroll
        for (int q = 0; q < HH / 4; ++q) { wA[q].f = rA[q]; wB[q].f = rB[q]; }
    }

    float c = 0.0f, hval = 0.0f;
    if (tid < HH) h_sh[0][tid] = 0.0f;
    __syncthreads();

    // xg row pointers: gate g0 at +0, gate g0+1 at +HH (same t,b row)
    const float* xg = g_xg + (size_t)b * G4 + (g0 * HH + j);
    const size_t ts = (size_t)BB * G4;

    float curA[2], curB[2], nxtA[2], nxtB[2];
    curA[0] = __ldcs(&xg[0]);       curB[0] = __ldcs(&xg[HH]);
    curA[1] = __ldcs(&xg[ts]);      curB[1] = __ldcs(&xg[ts + HH]);

    int p = 0;
    for (int tg = 0; tg < TT; tg += 2) {
        // prefetch steps tg+2, tg+3 for both gates
        {
            size_t o2 = (size_t)((tg + 2 < TT) ? tg + 2 : TT - 1) * ts;
            size_t o3 = (size_t)((tg + 3 < TT) ? tg + 3 : TT - 1) * ts;
            nxtA[0] = __ldcs(&xg[o2]);      nxtB[0] = __ldcs(&xg[o2 + HH]);
            nxtA[1] = __ldcs(&xg[o3]);      nxtB[1] = __ldcs(&xg[o3 + HH]);
        }

        #pragma unroll
        for (int i = 0; i < 2; ++i) {
            // 4 independent chains; each h float4 feeds all four
            unsigned long long A0 = 0ULL, A1 = 0ULL, B0 = 0ULL, B1 = 0ULL;
            const float4* hb = (const float4*)h_sh[p];
            #pragma unroll
            for (int q = 0; q < HH / 4; ++q) {
                f4u h4; h4.f = hb[q];            // broadcast LDS.128
                A0 = ffma2(wA[q].u.x, h4.u.x, A0);
                A1 = ffma2(wA[q].u.y, h4.u.y, A1);
                B0 = ffma2(wB[q].u.x, h4.u.x, B0);
                B1 = ffma2(wB[q].u.y, h4.u.y, B1);
            }
            f2u sA, sB;
            sA.u = fadd2(A0, A1);
            sB.u = fadd2(B0, B1);
            float gate0 = (sA.f.x + sA.f.y) + (i ? curA[1] : curA[0]);
            float gate1 = (sB.f.x + sB.f.y) + (i ? curB[1] : curB[0]);

            // activations: gp=0 -> sig(i), sig(f); gp=1 -> tanh(g), sig(o)
            float xx0 = gp ? 2.0f * gate0 : gate0;
            float s0  = sig_(xx0);
            float a0  = gp ? fmaf(2.0f, s0, -1.0f) : s0;   // i  or tanh(g)
            float a1  = sig_(gate1);                       // f  or sig(o)

            // leader (gp=0) pulls g,o from partner (2 width-2 shfls)
            float gg = __shfl_down_sync(pmask, a0, 1, 2);
            float og = __shfl_down_sync(pmask, a1, 1, 2);
            if (gp == 0) {
                c    = a1 * c + a0 * gg;       // f*c + i*g
                hval = og * tanh_(c);
                h_sh[p ^ 1][j] = hval;         // write OTHER buffer
            }
            __syncthreads();
            p ^= 1;
        }

        curA[0] = nxtA[0]; curA[1] = nxtA[1];
        curB[0] = nxtB[0]; curB[1] = nxtB[1];
    }

    if (gp == 0) out[b * HH + j] = hval;
}

// ---- launch ------------------------------------------------------------
extern "C" void kernel_launch(void* const* d_in, const int* in_sizes, int n_in,
                              void* d_out, int out_size) {
    const float* x   = (const float*)d_in[0];   // [64,2048,200]
    const float* Wih = (const float*)d_in[1];   // [400,200]
    const float* Whh = (const float*)d_in[2];   // [400,100]
    const float* bih = (const float*)d_in[3];   // [400]
    const float* bhh = (const float*)d_in[4];   // [400]
    float* out = (float*)d_out;                 // [64,100]

    proj_kernel<<<dim3(TT * BB / 64, 4), 200>>>(x, Wih, bih, bhh);
    scan_kernel<<<BB, 200>>>(Whh, out);
}